// round 16
// baseline (speedup 1.0000x reference)
#include <cuda_runtime.h>
#include <cuda_fp16.h>
#include <cstdint>

#define HID 512
#define BATCH 512
#define G4 2048
#define NCH0 9
#define NCH1 16
#define SEQ 128
#define FUT 48
#define TF_DIM 24
#define OUT_DIM 8

#define THREADS 512
#define A_TILE_B 8192
#define B_TILE_B 16384
#define SLOT_B (2 * A_TILE_B + 2 * B_TILE_B)   // 49152: [A0|A1|B0B1]
#define MBAR_OFF (2 * SLOT_B)                  // 98304  (2-slot ring)
#define SMEM_B (MBAR_OFF + 64)                 // 98368 -> 2 CTAs/SM (exactly r14)
#define CHSLAB 65536                           // bytes per (chunk, full-batch) A slab

// ---------------- persistent device buffers (chunk-tiled, pre-swizzled) ----------
__device__ __align__(256) __half g_w0[16 * NCH0 * 128 * 64];
__device__ __align__(256) __half g_w1[16 * NCH1 * 128 * 64];
__device__ __align__(256) __half g_xp[SEQ * BATCH * 64];
__device__ __align__(256) __half g_h0[2][BATCH * HID];
__device__ __align__(256) __half g_h1[2][BATCH * HID];
__device__ __align__(256) float g_h1f[BATCH * HID];
__device__ __align__(256) float g_pg[128 * 512 * 16];   // partial gates, 4MB
__device__ __align__(256) float g_c0[BATCH * HID];
__device__ __align__(256) float g_c1[BATCH * HID];
__device__ __align__(256) float g_b0[G4];
__device__ __align__(256) float g_b1[G4];

// ---------------- helpers ----------------
__device__ __forceinline__ int swz(int k, int r) {
    return (((k >> 3) ^ (r & 7)) << 3) | (k & 7);
}
__device__ __forceinline__ uint32_t smem_u32(const void* p) {
    uint32_t a;
    asm("{ .reg .u64 t; cvta.to.shared.u64 t, %1; cvt.u32.u64 %0, t; }" : "=r"(a) : "l"(p));
    return a;
}
__device__ __forceinline__ void cpbulk(uint32_t dst, const void* src, uint32_t bytes,
                                       uint32_t mbar) {
    asm volatile(
        "cp.async.bulk.shared::cluster.global.mbarrier::complete_tx::bytes "
        "[%0], [%1], %2, [%3];"
        :: "r"(dst), "l"(src), "r"(bytes), "r"(mbar) : "memory");
}
#define FENCE_ASYNC() asm volatile("fence.proxy.async.shared::cta;" ::: "memory")
#define MBAR_INIT(a, n) asm volatile("mbarrier.init.shared.b64 [%0], %1;" :: "r"(a), "r"(n) : "memory")
#define MBAR_EXPECT_TX(a, tx) asm volatile("mbarrier.arrive.expect_tx.shared.b64 _, [%0], %1;" :: "r"(a), "r"(tx) : "memory")
#define MBAR_ARRIVE(a) asm volatile("mbarrier.arrive.shared.b64 _, [%0];" :: "r"(a) : "memory")

__device__ __forceinline__ void mbar_wait(uint32_t mbar, uint32_t parity) {
    asm volatile(
        "{\n\t.reg .pred P1;\n\t"
        "WL_%=:\n\t"
        "mbarrier.try_wait.parity.acquire.cta.shared::cta.b64 P1, [%0], %1, 0x989680;\n\t"
        "@P1 bra.uni WD_%=;\n\t"
        "bra.uni WL_%=;\n\t"
        "WD_%=:\n\t}"
        :: "r"(mbar), "r"(parity) : "memory");
}
__device__ __forceinline__ void ldsm4(uint32_t* r, uint32_t addr) {
    asm volatile("ldmatrix.sync.aligned.m8n8.x4.shared.b16 {%0,%1,%2,%3}, [%4];"
                 : "=r"(r[0]), "=r"(r[1]), "=r"(r[2]), "=r"(r[3]) : "r"(addr));
}
__device__ __forceinline__ void mma16816h(uint32_t* d, const uint32_t* a,
                                          const uint32_t* b) {
    asm volatile(
        "mma.sync.aligned.m16n8k16.row.col.f16.f16.f16.f16 "
        "{%0,%1}, {%2,%3,%4,%5}, {%6,%7}, {%0,%1};"
        : "+r"(d[0]), "+r"(d[1])
        : "r"(a[0]), "r"(a[1]), "r"(a[2]), "r"(a[3]), "r"(b[0]), "r"(b[1]));
}
__device__ __forceinline__ float sigf(float x) { return 1.0f / (1.0f + __expf(-x)); }

// ---------------- prep kernels ----------------
__global__ void prep_w0(const float* __restrict__ wih, const float* __restrict__ whh) {
    int idx = blockIdx.x * blockDim.x + threadIdx.x;
    if (idx >= G4 * (64 + HID)) return;
    int n = idx / (64 + HID), k = idx - n * (64 + HID);
    int row = (n & 3) * HID + (n >> 2);
    float v;
    if (k < 64) v = (k < 32) ? wih[row * 32 + k] : 0.0f;
    else        v = whh[row * HID + (k - 64)];
    int r = n & 127;
    size_t dst = ((size_t)((n >> 7) * NCH0 + (k >> 6)) * 128 + r) * 64 + swz(k & 63, r);
    g_w0[dst] = __float2half(v);
}
__global__ void prep_w1(const float* __restrict__ wih, const float* __restrict__ whh) {
    int idx = blockIdx.x * blockDim.x + threadIdx.x;
    if (idx >= G4 * 1024) return;
    int n = idx >> 10, k = idx & 1023;
    int row = (n & 3) * HID + (n >> 2);
    float v = (k < HID) ? wih[row * HID + k] : whh[row * HID + (k - HID)];
    int r = n & 127;
    size_t dst = ((size_t)((n >> 7) * NCH1 + (k >> 6)) * 128 + r) * 64 + swz(k & 63, r);
    g_w1[dst] = __float2half(v);
}
__global__ void prep_misc(const float* __restrict__ x,
                          const float* __restrict__ h0in, const float* __restrict__ c0in,
                          const float* __restrict__ bi0, const float* __restrict__ bh0,
                          const float* __restrict__ bi1, const float* __restrict__ bh1) {
    int idx = blockIdx.x * blockDim.x + threadIdx.x;
    if (idx < SEQ * BATCH * 64) {   // xpad
        int k = idx & 63, b = (idx >> 6) & 511, t = idx >> 15;
        float v = (k < 32) ? x[((size_t)t * BATCH + b) * 32 + k] : 0.0f;
        g_xp[((size_t)t * BATCH + b) * 64 + swz(k, b)] = __float2half(v);
    }
    if (idx < G4) {
        int row = (idx & 3) * HID + (idx >> 2);
        g_b0[idx] = bi0[row] + bh0[row];
        g_b1[idx] = bi1[row] + bh1[row];
    }
    if (idx < BATCH * HID) {
        int b = idx >> 9, j = idx & (HID - 1);
        size_t dst = ((size_t)(j >> 6) * BATCH + b) * 64 + swz(j & 63, b);
        g_h0[0][dst] = __float2half(h0in[j]);
        g_h1[0][dst] = __float2half(h0in[HID + j]);
        g_c0[idx] = c0in[j];
        g_c1[idx] = c0in[HID + j];
    }
}

// ---------------- cell parameters ----------------
struct CellP {
    const __half* slab0;    // chunk0 A slab (encoder xp row) or null
    const __half* a1;       // h chunks (local 0..7 after chunk0)
    const __half* a2;       // h chunks local 8..15 (encoder l1)
    const __half* wt;       // weight tile base
    int nch, woff, wstride;
    const float* bias;
    float* cbuf;
    __half* hOut;
    float* hOutF;
    float* pgOut;           // l1a: write raw partial gates, skip LSTM epilogue
    const float* pgIn;      // l1b: add partial gates before epilogue
    // decode-l0 fc prologue (chunk0 A built in-place in slot0 A region)
    const float* h1fprev;
    const float* fcw;
    const float* fcb;
    const float* tfrow;
    float* outrow;
};

// ------------ fused LSTM cell (16 warps, 2-slot ring, 2 CTAs/SM) ---------------
__global__ __launch_bounds__(THREADS, 2)
void lstm_cell(CellP A0, CellP A1)
{
    const CellP P = blockIdx.z ? A1 : A0;
    extern __shared__ char smem_raw[];
    const uint32_t sb = smem_u32(smem_raw);
    const uint32_t mb = sb + MBAR_OFF;          // full[0..1] @ +0,8 ; free[0..1] @ +16,24
    const int tid = threadIdx.x;
    const int l = tid & 31, w = tid >> 5;
    const int wm = w & 3;
    const int wn = w >> 2;
    const int n0 = blockIdx.x * 128;
    const int m0 = blockIdx.y * 64;
    const int nch = P.nch;
    const int nslots = (nch + 1) >> 1;
    const bool sk0 = (P.h1fprev != nullptr);    // decode l0: chunk0 A built in smem

    if (tid == 0) {
#pragma unroll
        for (int s = 0; s < 2; ++s) MBAR_INIT(mb + s * 8, 1);       // full (tx)
#pragma unroll
        for (int s = 0; s < 2; ++s) MBAR_INIT(mb + 16 + s * 8, 16); // free (16 warps)
    }
    __syncthreads();

    const char* wbase = (const char*)P.wt +
        ((size_t)blockIdx.x * P.wstride + P.woff) * B_TILE_B;

    auto srcA = [&](int c) -> const char* {
        if (c == 0 && P.slab0 != nullptr)
            return (const char*)P.slab0 + (size_t)m0 * 128;
        int s1 = c - ((P.slab0 != nullptr || sk0) ? 1 : 0);
        const __half* base = (s1 < 8) ? P.a1 : P.a2;
        if (s1 >= 8) s1 -= 8;
        return (const char*)base + (size_t)s1 * CHSLAB + (size_t)m0 * 128;
    };

    auto issue = [&](int k) {
        if (k >= 2)   // ring reuse: wait until all 16 warps consumed slot k-2
            mbar_wait(mb + 16 + (uint32_t)(k & 1) * 8, (uint32_t)((k / 2 - 1) & 1));
        const int c0 = 2 * k;
        const bool has2 = (c0 + 1 < nch);
        const bool a0load = !(sk0 && k == 0);   // decode: chunk0 A written by prologue
        const uint32_t st = sb + (uint32_t)(k & 1) * SLOT_B;
        const uint32_t m = mb + (uint32_t)(k & 1) * 8;
        FENCE_ASYNC();
        uint32_t tx = (has2 ? 2u : 1u) * B_TILE_B;
        if (a0load) tx += A_TILE_B;
        if (has2) tx += A_TILE_B;
        MBAR_EXPECT_TX(m, tx);
        if (a0load) cpbulk(st, srcA(c0), A_TILE_B, m);
        if (has2) cpbulk(st + A_TILE_B, srcA(c0 + 1), A_TILE_B, m);
        cpbulk(st + 2 * A_TILE_B, wbase + (size_t)c0 * B_TILE_B,
               (has2 ? 2u : 1u) * B_TILE_B, m);
    };

    if (tid == 0) {
        issue(0);
        if (nslots > 1) issue(1);
    }

    // decode-l0 prologue: y = fc(h1f) fp32 (identical math to old fc_head),
    // write swizzled [y|tf|0] directly into slot0's (unloaded) A region,
    // x==0 CTAs also store the output row. Disjoint from slot0's B bulk loads.
    if (sk0) {
        const int rr = tid >> 3, o = tid & 7;   // row 0..63, out 0..7
        const int b = m0 + rr;
        const float4* h4 = (const float4*)(P.h1fprev + (size_t)b * HID);
        const float4* w4 = (const float4*)(P.fcw + (size_t)o * HID);
        float s = P.fcb[o];
#pragma unroll 4
        for (int j = 0; j < HID / 4; ++j) {
            float4 a = __ldg(h4 + j), wv = __ldg(w4 + j);
            s += a.x * wv.x + a.y * wv.y + a.z * wv.z + a.w * wv.w;
        }
        char* rowp = smem_raw + rr * 128;       // slot0 A region, offset 0
        *(__half*)(rowp + 2 * swz(o, rr)) = __float2half(s);
#pragma unroll
        for (int m = 0; m < 3; ++m) {
            int kk = 8 + o * 3 + m;
            float v = __ldg(&P.tfrow[(size_t)b * TF_DIM + o * 3 + m]);
            *(__half*)(rowp + 2 * swz(kk, rr)) = __float2half(v);
        }
#pragma unroll
        for (int z = 0; z < 4; ++z) {
            int kk = 32 + o * 4 + z;
            *(__half*)(rowp + 2 * swz(kk, rr)) = __half(0.0f);
        }
        if (blockIdx.x == 0)
            P.outrow[(size_t)b * OUT_DIM + o] = s;
        __syncthreads();
    }

    float acc[4][4];
#pragma unroll
    for (int nt = 0; nt < 4; ++nt)
#pragma unroll
        for (int i = 0; i < 4; ++i) acc[nt][i] = 0.0f;

    const uint32_t aRow = (uint32_t)(wm * 16 + (l & 15));
    const uint32_t aQl = (uint32_t)(l >> 4);
    const uint32_t bRowB = (uint32_t)(wn * 32 + (l & 7) + ((l >> 4) & 1) * 8);
    const uint32_t bQl = (uint32_t)((l >> 3) & 1);

    auto chunk_mma = [&](uint32_t aB, uint32_t bB) {
        uint32_t d16[4][2];
#pragma unroll
        for (int nt = 0; nt < 4; ++nt) { d16[nt][0] = 0u; d16[nt][1] = 0u; }
#pragma unroll
        for (int ks = 0; ks < 4; ++ks) {
            const uint32_t qa = aQl + ks * 2;
            uint32_t a[4];
            ldsm4(a, aB + aRow * 128 + ((qa ^ (aRow & 7)) << 4));
            uint32_t b[4][2];
#pragma unroll
            for (int ntp = 0; ntp < 2; ++ntp) {
                const uint32_t br = bRowB + ntp * 16;
                const uint32_t qb = bQl + ks * 2;
                uint32_t r4[4];
                ldsm4(r4, bB + br * 128 + ((qb ^ (br & 7)) << 4));
                b[ntp * 2][0] = r4[0]; b[ntp * 2][1] = r4[1];
                b[ntp * 2 + 1][0] = r4[2]; b[ntp * 2 + 1][1] = r4[3];
            }
#pragma unroll
            for (int nt = 0; nt < 4; ++nt)
                mma16816h(d16[nt], a, b[nt]);
        }
#pragma unroll
        for (int nt = 0; nt < 4; ++nt) {
            float2 p0 = __half22float2(*(const __half2*)&d16[nt][0]);
            float2 p1 = __half22float2(*(const __half2*)&d16[nt][1]);
            acc[nt][0] += p0.x; acc[nt][1] += p0.y;
            acc[nt][2] += p1.x; acc[nt][3] += p1.y;
        }
    };

    for (int slot = 0; slot < nslots; ++slot) {
        mbar_wait(mb + (uint32_t)(slot & 1) * 8, (uint32_t)((slot / 2) & 1));
        const uint32_t stage = sb + (uint32_t)(slot & 1) * SLOT_B;
        chunk_mma(stage, stage + 2 * A_TILE_B);
        if (2 * slot + 1 < nch)
            chunk_mma(stage + A_TILE_B, stage + 2 * A_TILE_B + B_TILE_B);
        if (l == 0) MBAR_ARRIVE(mb + 16 + (uint32_t)(slot & 1) * 8);
        if (tid == 0 && slot + 2 < nslots) issue(slot + 2);
    }

    // ---- partial-gate write path (l1a) ----
    const size_t pgbase =
        (((size_t)blockIdx.x * 8 + blockIdx.y) * THREADS + tid) * 16;
    if (P.pgOut != nullptr) {
#pragma unroll
        for (int nt = 0; nt < 4; ++nt)
            *(float4*)(P.pgOut + pgbase + nt * 4) =
                make_float4(acc[nt][0], acc[nt][1], acc[nt][2], acc[nt][3]);
        return;
    }

    // ---- epilogue ----
    const bool odd = (l & 1) != 0;
#pragma unroll
    for (int nt = 0; nt < 4; ++nt) {
        float* cc = acc[nt];
        if (P.pgIn != nullptr) {
            float4 pg = *(const float4*)(P.pgIn + pgbase + nt * 4);
            cc[0] += pg.x; cc[1] += pg.y; cc[2] += pg.z; cc[3] += pg.w;
        }
        float send1 = odd ? cc[0] : cc[2];
        float send2 = odd ? cc[1] : cc[3];
        float r1 = __shfl_xor_sync(0xffffffffu, send1, 1);
        float r2 = __shfl_xor_sync(0xffffffffu, send2, 1);
        float gi, gf, gg, go;
        if (!odd) { gi = cc[0]; gf = cc[1]; gg = r1; go = r2; }
        else      { gi = r1;    gf = r2;    gg = cc[2]; go = cc[3]; }

        const int j = ((n0 + wn * 32 + nt * 8) >> 2) + ((l & 3) >> 1);
        const float4 b4 = *(const float4*)(P.bias + 4 * j);
        gi += b4.x; gf += b4.y; gg += b4.z; go += b4.w;

        const int bglob = m0 + wm * 16 + (l >> 2) + (odd ? 8 : 0);
        const int ix = bglob * HID + j;
        float cp = P.cbuf[ix];
        float cn = sigf(gf) * cp + sigf(gi) * tanhf(gg);
        float hn = sigf(go) * tanhf(cn);
        P.cbuf[ix] = cn;
        P.hOut[((size_t)(j >> 6) * BATCH + bglob) * 64 + swz(j & 63, bglob)] =
            __float2half(hn);
        if (P.hOutF != nullptr) P.hOutF[ix] = hn;
    }
}

// ---------------- final output row ----------------
__global__ void fc_out(const float* __restrict__ h1f,
                       const float* __restrict__ fcw, const float* __restrict__ fcb,
                       float* __restrict__ outp) {
    int idx = blockIdx.x * blockDim.x + threadIdx.x;   // 4096
    int b = idx >> 3, o = idx & 7;
    const float4* h4 = (const float4*)(h1f + (size_t)b * HID);
    const float4* w4 = (const float4*)(fcw + (size_t)o * HID);
    float s = fcb[o];
#pragma unroll 4
    for (int j = 0; j < HID / 4; ++j) {
        float4 a = h4[j], wv = w4[j];
        s += a.x * wv.x + a.y * wv.y + a.z * wv.z + a.w * wv.w;
    }
    outp[b * OUT_DIM + o] = s;
}

// ---------------- host orchestration ----------------
extern "C" void kernel_launch(void* const* d_in, const int* in_sizes, int n_in,
                              void* d_out, int out_size) {
    const float* x     = (const float*)d_in[0];
    const float* ft    = (const float*)d_in[1];
    const float* h0in  = (const float*)d_in[2];
    const float* c0in  = (const float*)d_in[3];
    const float* w_ih0 = (const float*)d_in[4];
    const float* w_hh0 = (const float*)d_in[5];
    const float* b_ih0 = (const float*)d_in[6];
    const float* b_hh0 = (const float*)d_in[7];
    const float* w_ih1 = (const float*)d_in[8];
    const float* w_hh1 = (const float*)d_in[9];
    const float* b_ih1 = (const float*)d_in[10];
    const float* b_hh1 = (const float*)d_in[11];
    const float* fcw   = (const float*)d_in[12];
    const float* fcb   = (const float*)d_in[13];
    float* out = (float*)d_out;

    cudaFuncSetAttribute(lstm_cell, cudaFuncAttributeMaxDynamicSharedMemorySize, SMEM_B);

    __half *w0p, *w1p, *xp, *h0p, *h1p;
    float *h1fp, *pgp, *c0p, *c1p, *b0p, *b1p;
    cudaGetSymbolAddress((void**)&w0p, g_w0);
    cudaGetSymbolAddress((void**)&w1p, g_w1);
    cudaGetSymbolAddress((void**)&xp, g_xp);
    cudaGetSymbolAddress((void**)&h0p, g_h0);
    cudaGetSymbolAddress((void**)&h1p, g_h1);
    cudaGetSymbolAddress((void**)&h1fp, g_h1f);
    cudaGetSymbolAddress((void**)&pgp, g_pg);
    cudaGetSymbolAddress((void**)&c0p, g_c0);
    cudaGetSymbolAddress((void**)&c1p, g_c1);
    cudaGetSymbolAddress((void**)&b0p, g_b0);
    cudaGetSymbolAddress((void**)&b1p, g_b1);

    prep_w0<<<(G4 * (64 + HID) + 255) / 256, 256>>>(w_ih0, w_hh0);
    prep_w1<<<(G4 * 1024 + 255) / 256, 256>>>(w_ih1, w_hh1);
    prep_misc<<<(SEQ * BATCH * 64 + 255) / 256, 256>>>(x, h0in, c0in,
                                                       b_ih0, b_hh0, b_ih1, b_hh1);

    const int SN = BATCH * HID;
    CellP Z = {};

    auto mk_l0enc = [&](int s) {
        CellP a = {};
        a.slab0 = xp + (size_t)s * BATCH * 64;
        a.a1 = h0p + (size_t)(s & 1) * SN;
        a.wt = w0p; a.nch = NCH0; a.woff = 0; a.wstride = NCH0;
        a.bias = b0p; a.cbuf = c0p;
        a.hOut = h0p + (size_t)((s + 1) & 1) * SN;
        return a;
    };
    auto mk_l1full = [&](int s, bool wf) {
        CellP a = {};
        a.a1 = h0p + (size_t)((s + 1) & 1) * SN;
        a.a2 = h1p + (size_t)(s & 1) * SN;
        a.wt = w1p; a.nch = NCH1; a.woff = 0; a.wstride = NCH1;
        a.bias = b1p; a.cbuf = c1p;
        a.hOut = h1p + (size_t)((s + 1) & 1) * SN;
        a.hOutF = wf ? h1fp : nullptr;
        return a;
    };
    auto mk_l0dec = [&](int s, int d) {   // fc prologue builds chunk0 in slot0 A region
        CellP a = {};
        a.a1 = h0p + (size_t)(s & 1) * SN;
        a.wt = w0p; a.nch = NCH0; a.woff = 0; a.wstride = NCH0;
        a.bias = b0p; a.cbuf = c0p;
        a.hOut = h0p + (size_t)((s + 1) & 1) * SN;
        a.h1fprev = h1fp; a.fcw = fcw; a.fcb = fcb;
        a.tfrow = ft + (size_t)d * BATCH * TF_DIM;
        a.outrow = out + (size_t)d * BATCH * OUT_DIM;
        return a;
    };
    auto mk_l1a = [&](int s) {   // h1_old half -> partial gates
        CellP a = {};
        a.a1 = h1p + (size_t)(s & 1) * SN;
        a.wt = w1p; a.nch = 8; a.woff = 8; a.wstride = NCH1;
        a.pgOut = pgp;
        return a;
    };
    auto mk_l1b = [&](int s) {   // h0_new half + partial add
        CellP a = {};
        a.a1 = h0p + (size_t)((s + 1) & 1) * SN;
        a.wt = w1p; a.nch = 8; a.woff = 0; a.wstride = NCH1;
        a.pgIn = pgp;
        a.bias = b1p; a.cbuf = c1p;
        a.hOut = h1p + (size_t)((s + 1) & 1) * SN;
        a.hOutF = h1fp;
        return a;
    };

    const dim3 gridS(16, 8, 1), gridC(16, 8, 2);

    // encoder: pair l1(t) with independent l0(t+1)
    lstm_cell<<<gridS, THREADS, SMEM_B>>>(mk_l0enc(0), Z);
    for (int t = 0; t < SEQ - 1; ++t)
        lstm_cell<<<gridC, THREADS, SMEM_B>>>(mk_l1full(t, false), mk_l0enc(t + 1));
    lstm_cell<<<gridS, THREADS, SMEM_B>>>(mk_l1full(SEQ - 1, true), Z);

    // autoregressive decode: pairC(l0dec-with-fc(d), l1a(d)) -> l1b(d); 2 launches/step
    for (int d = 0; d < FUT - 1; ++d) {
        const int s = SEQ + d;
        lstm_cell<<<gridC, THREADS, SMEM_B>>>(mk_l0dec(s, d), mk_l1a(s));
        lstm_cell<<<gridS, THREADS, SMEM_B>>>(mk_l1b(s), Z);
    }
    fc_out<<<16, 256>>>(h1fp, fcw, fcb, out + (size_t)(FUT - 1) * BATCH * OUT_DIM);
}

// round 17
// speedup vs baseline: 1.4049x; 1.4049x over previous
#include <cuda_runtime.h>
#include <cuda_fp16.h>
#include <cstdint>

#define HID 512
#define BATCH 512
#define G4 2048
#define NCH0 9
#define NCH1 16
#define SEQ 128
#define FUT 48
#define TF_DIM 24
#define OUT_DIM 8

#define THREADS 512
#define A_TILE_B 8192
#define B_TILE_B 16384
#define SLOT_B (2 * A_TILE_B + 2 * B_TILE_B)   // 49152: [A0|A1|B0B1]
#define MBAR_OFF (2 * SLOT_B)                  // 98304  (2-slot ring)
#define SMEM_B (MBAR_OFF + 64)                 // 98368 -> 2 CTAs/SM
#define CHSLAB 65536                           // bytes per (chunk, full-batch) A slab

// ---------------- persistent device buffers (chunk-tiled, pre-swizzled) ----------
__device__ __align__(256) __half g_w0[16 * NCH0 * 128 * 64];
__device__ __align__(256) __half g_w1[16 * NCH1 * 128 * 64];
__device__ __align__(256) __half g_xp[SEQ * BATCH * 64];
__device__ __align__(256) __half g_h0[2][BATCH * HID];
__device__ __align__(256) __half g_h1[2][BATCH * HID];
__device__ __align__(256) float g_h1f[BATCH * HID];
__device__ __align__(256) float g_pg[128 * 512 * 16];   // partial gates, 4MB
__device__ __align__(256) float g_yp[16 * BATCH * OUT_DIM];  // fc partials, 256KB
__device__ __align__(256) float g_c0[BATCH * HID];
__device__ __align__(256) float g_c1[BATCH * HID];
__device__ __align__(256) float g_b0[G4];
__device__ __align__(256) float g_b1[G4];

// ---------------- helpers ----------------
__device__ __forceinline__ int swz(int k, int r) {
    return (((k >> 3) ^ (r & 7)) << 3) | (k & 7);
}
__device__ __forceinline__ uint32_t smem_u32(const void* p) {
    uint32_t a;
    asm("{ .reg .u64 t; cvta.to.shared.u64 t, %1; cvt.u32.u64 %0, t; }" : "=r"(a) : "l"(p));
    return a;
}
__device__ __forceinline__ void cpbulk(uint32_t dst, const void* src, uint32_t bytes,
                                       uint32_t mbar) {
    asm volatile(
        "cp.async.bulk.shared::cluster.global.mbarrier::complete_tx::bytes "
        "[%0], [%1], %2, [%3];"
        :: "r"(dst), "l"(src), "r"(bytes), "r"(mbar) : "memory");
}
#define FENCE_ASYNC() asm volatile("fence.proxy.async.shared::cta;" ::: "memory")
#define MBAR_INIT(a, n) asm volatile("mbarrier.init.shared.b64 [%0], %1;" :: "r"(a), "r"(n) : "memory")
#define MBAR_EXPECT_TX(a, tx) asm volatile("mbarrier.arrive.expect_tx.shared.b64 _, [%0], %1;" :: "r"(a), "r"(tx) : "memory")
#define MBAR_ARRIVE(a) asm volatile("mbarrier.arrive.shared.b64 _, [%0];" :: "r"(a) : "memory")

__device__ __forceinline__ void mbar_wait(uint32_t mbar, uint32_t parity) {
    asm volatile(
        "{\n\t.reg .pred P1;\n\t"
        "WL_%=:\n\t"
        "mbarrier.try_wait.parity.acquire.cta.shared::cta.b64 P1, [%0], %1, 0x989680;\n\t"
        "@P1 bra.uni WD_%=;\n\t"
        "bra.uni WL_%=;\n\t"
        "WD_%=:\n\t}"
        :: "r"(mbar), "r"(parity) : "memory");
}
__device__ __forceinline__ void ldsm4(uint32_t* r, uint32_t addr) {
    asm volatile("ldmatrix.sync.aligned.m8n8.x4.shared.b16 {%0,%1,%2,%3}, [%4];"
                 : "=r"(r[0]), "=r"(r[1]), "=r"(r[2]), "=r"(r[3]) : "r"(addr));
}
__device__ __forceinline__ void mma16816h(uint32_t* d, const uint32_t* a,
                                          const uint32_t* b) {
    asm volatile(
        "mma.sync.aligned.m16n8k16.row.col.f16.f16.f16.f16 "
        "{%0,%1}, {%2,%3,%4,%5}, {%6,%7}, {%0,%1};"
        : "+r"(d[0]), "+r"(d[1])
        : "r"(a[0]), "r"(a[1]), "r"(a[2]), "r"(a[3]), "r"(b[0]), "r"(b[1]));
}
__device__ __forceinline__ float sigf(float x) { return 1.0f / (1.0f + __expf(-x)); }

// ---------------- prep kernels ----------------
__global__ void prep_w0(const float* __restrict__ wih, const float* __restrict__ whh) {
    int idx = blockIdx.x * blockDim.x + threadIdx.x;
    if (idx >= G4 * (64 + HID)) return;
    int n = idx / (64 + HID), k = idx - n * (64 + HID);
    int row = (n & 3) * HID + (n >> 2);
    float v;
    if (k < 64) v = (k < 32) ? wih[row * 32 + k] : 0.0f;
    else        v = whh[row * HID + (k - 64)];
    int r = n & 127;
    size_t dst = ((size_t)((n >> 7) * NCH0 + (k >> 6)) * 128 + r) * 64 + swz(k & 63, r);
    g_w0[dst] = __float2half(v);
}
__global__ void prep_w1(const float* __restrict__ wih, const float* __restrict__ whh) {
    int idx = blockIdx.x * blockDim.x + threadIdx.x;
    if (idx >= G4 * 1024) return;
    int n = idx >> 10, k = idx & 1023;
    int row = (n & 3) * HID + (n >> 2);
    float v = (k < HID) ? wih[row * HID + k] : whh[row * HID + (k - HID)];
    int r = n & 127;
    size_t dst = ((size_t)((n >> 7) * NCH1 + (k >> 6)) * 128 + r) * 64 + swz(k & 63, r);
    g_w1[dst] = __float2half(v);
}
__global__ void prep_misc(const float* __restrict__ x,
                          const float* __restrict__ h0in, const float* __restrict__ c0in,
                          const float* __restrict__ bi0, const float* __restrict__ bh0,
                          const float* __restrict__ bi1, const float* __restrict__ bh1) {
    int idx = blockIdx.x * blockDim.x + threadIdx.x;
    if (idx < SEQ * BATCH * 64) {   // xpad
        int k = idx & 63, b = (idx >> 6) & 511, t = idx >> 15;
        float v = (k < 32) ? x[((size_t)t * BATCH + b) * 32 + k] : 0.0f;
        g_xp[((size_t)t * BATCH + b) * 64 + swz(k, b)] = __float2half(v);
    }
    if (idx < G4) {
        int row = (idx & 3) * HID + (idx >> 2);
        g_b0[idx] = bi0[row] + bh0[row];
        g_b1[idx] = bi1[row] + bh1[row];
    }
    if (idx < BATCH * HID) {
        int b = idx >> 9, j = idx & (HID - 1);
        size_t dst = ((size_t)(j >> 6) * BATCH + b) * 64 + swz(j & 63, b);
        g_h0[0][dst] = __float2half(h0in[j]);
        g_h1[0][dst] = __float2half(h0in[HID + j]);
        g_c0[idx] = c0in[j];
        g_c1[idx] = c0in[HID + j];
    }
}

// ---------------- cell parameters ----------------
struct CellP {
    const __half* slab0;    // chunk0 A slab (encoder xp row) or null
    const __half* a1;       // h chunks (local 0..7 after chunk0)
    const __half* a2;       // h chunks local 8..15 (encoder l1)
    const __half* wt;       // weight tile base
    int nch, woff, wstride;
    const float* bias;
    float* cbuf;
    __half* hOut;
    float* hOutF;
    float* pgOut;           // l1a: write raw partial gates, skip LSTM epilogue
    const float* pgIn;      // l1b: add partial gates before epilogue
    // fc split machinery
    float* ypOut;           // l1b/l1full-last: write per-CTA fc partials (epilogue)
    const float* fcw;       //   fcw rows for partial-fc
    const float* ypIn;      // decode-l0: gather fc partials (light prologue)
    const float* fcb;
    const float* tfrow;
    float* outrow;
};

// ------------ fused LSTM cell (16 warps, 2-slot ring, 2 CTAs/SM) ---------------
__global__ __launch_bounds__(THREADS, 2)
void lstm_cell(CellP A0, CellP A1)
{
    const CellP P = blockIdx.z ? A1 : A0;
    extern __shared__ char smem_raw[];
    const uint32_t sb = smem_u32(smem_raw);
    const uint32_t mb = sb + MBAR_OFF;          // full[0..1] @ +0,8 ; free[0..1] @ +16,24
    const int tid = threadIdx.x;
    const int l = tid & 31, w = tid >> 5;
    const int wm = w & 3;
    const int wn = w >> 2;
    const int n0 = blockIdx.x * 128;
    const int m0 = blockIdx.y * 64;
    const int nch = P.nch;
    const int nslots = (nch + 1) >> 1;
    const bool sk0 = (P.ypIn != nullptr);       // decode l0: chunk0 A built in smem

    if (tid == 0) {
#pragma unroll
        for (int s = 0; s < 2; ++s) MBAR_INIT(mb + s * 8, 1);       // full (tx)
#pragma unroll
        for (int s = 0; s < 2; ++s) MBAR_INIT(mb + 16 + s * 8, 16); // free (16 warps)
    }
    __syncthreads();

    const char* wbase = (const char*)P.wt +
        ((size_t)blockIdx.x * P.wstride + P.woff) * B_TILE_B;

    auto srcA = [&](int c) -> const char* {
        if (c == 0 && P.slab0 != nullptr)
            return (const char*)P.slab0 + (size_t)m0 * 128;
        int s1 = c - ((P.slab0 != nullptr || sk0) ? 1 : 0);
        const __half* base = (s1 < 8) ? P.a1 : P.a2;
        if (s1 >= 8) s1 -= 8;
        return (const char*)base + (size_t)s1 * CHSLAB + (size_t)m0 * 128;
    };

    auto issue = [&](int k) {
        if (k >= 2)   // ring reuse: wait until all 16 warps consumed slot k-2
            mbar_wait(mb + 16 + (uint32_t)(k & 1) * 8, (uint32_t)((k / 2 - 1) & 1));
        const int c0 = 2 * k;
        const bool has2 = (c0 + 1 < nch);
        const bool a0load = !(sk0 && k == 0);   // decode: chunk0 A written by prologue
        const uint32_t st = sb + (uint32_t)(k & 1) * SLOT_B;
        const uint32_t m = mb + (uint32_t)(k & 1) * 8;
        FENCE_ASYNC();
        uint32_t tx = (has2 ? 2u : 1u) * B_TILE_B;
        if (a0load) tx += A_TILE_B;
        if (has2) tx += A_TILE_B;
        MBAR_EXPECT_TX(m, tx);
        if (a0load) cpbulk(st, srcA(c0), A_TILE_B, m);
        if (has2) cpbulk(st + A_TILE_B, srcA(c0 + 1), A_TILE_B, m);
        cpbulk(st + 2 * A_TILE_B, wbase + (size_t)c0 * B_TILE_B,
               (has2 ? 2u : 1u) * B_TILE_B, m);
    };

    if (tid == 0) {
        issue(0);
        if (nslots > 1) issue(1);
    }

    // decode-l0 LIGHT prologue: gather fc partials (no redundant fc compute),
    // build swizzled [y|tf|0] chunk0 directly in slot0's (unloaded) A region.
    if (sk0) {
        const int rr = tid >> 3, o = tid & 7;   // row 0..63, out 0..7
        const int b = m0 + rr;
        float s = P.fcb[o];
#pragma unroll
        for (int xb = 0; xb < 16; ++xb)
            s += P.ypIn[((size_t)xb * BATCH + b) * OUT_DIM + o];
        char* rowp = smem_raw + rr * 128;       // slot0 A region
        *(__half*)(rowp + 2 * swz(o, rr)) = __float2half(s);
#pragma unroll
        for (int m = 0; m < 3; ++m) {
            int kk = 8 + o * 3 + m;
            float v = __ldg(&P.tfrow[(size_t)b * TF_DIM + o * 3 + m]);
            *(__half*)(rowp + 2 * swz(kk, rr)) = __float2half(v);
        }
#pragma unroll
        for (int z = 0; z < 4; ++z) {
            int kk = 32 + o * 4 + z;
            *(__half*)(rowp + 2 * swz(kk, rr)) = __half(0.0f);
        }
        if (blockIdx.x == 0)
            P.outrow[(size_t)b * OUT_DIM + o] = s;
        __syncthreads();
    }

    float acc[4][4];
#pragma unroll
    for (int nt = 0; nt < 4; ++nt)
#pragma unroll
        for (int i = 0; i < 4; ++i) acc[nt][i] = 0.0f;

    const uint32_t aRow = (uint32_t)(wm * 16 + (l & 15));
    const uint32_t aQl = (uint32_t)(l >> 4);
    const uint32_t bRowB = (uint32_t)(wn * 32 + (l & 7) + ((l >> 4) & 1) * 8);
    const uint32_t bQl = (uint32_t)((l >> 3) & 1);

    auto chunk_mma = [&](uint32_t aB, uint32_t bB) {
        uint32_t d16[4][2];
#pragma unroll
        for (int nt = 0; nt < 4; ++nt) { d16[nt][0] = 0u; d16[nt][1] = 0u; }
#pragma unroll
        for (int ks = 0; ks < 4; ++ks) {
            const uint32_t qa = aQl + ks * 2;
            uint32_t a[4];
            ldsm4(a, aB + aRow * 128 + ((qa ^ (aRow & 7)) << 4));
            uint32_t b[4][2];
#pragma unroll
            for (int ntp = 0; ntp < 2; ++ntp) {
                const uint32_t br = bRowB + ntp * 16;
                const uint32_t qb = bQl + ks * 2;
                uint32_t r4[4];
                ldsm4(r4, bB + br * 128 + ((qb ^ (br & 7)) << 4));
                b[ntp * 2][0] = r4[0]; b[ntp * 2][1] = r4[1];
                b[ntp * 2 + 1][0] = r4[2]; b[ntp * 2 + 1][1] = r4[3];
            }
#pragma unroll
            for (int nt = 0; nt < 4; ++nt)
                mma16816h(d16[nt], a, b[nt]);
        }
#pragma unroll
        for (int nt = 0; nt < 4; ++nt) {
            float2 p0 = __half22float2(*(const __half2*)&d16[nt][0]);
            float2 p1 = __half22float2(*(const __half2*)&d16[nt][1]);
            acc[nt][0] += p0.x; acc[nt][1] += p0.y;
            acc[nt][2] += p1.x; acc[nt][3] += p1.y;
        }
    };

    for (int slot = 0; slot < nslots; ++slot) {
        mbar_wait(mb + (uint32_t)(slot & 1) * 8, (uint32_t)((slot / 2) & 1));
        const uint32_t stage = sb + (uint32_t)(slot & 1) * SLOT_B;
        chunk_mma(stage, stage + 2 * A_TILE_B);
        if (2 * slot + 1 < nch)
            chunk_mma(stage + A_TILE_B, stage + 2 * A_TILE_B + B_TILE_B);
        if (l == 0) MBAR_ARRIVE(mb + 16 + (uint32_t)(slot & 1) * 8);
        if (tid == 0 && slot + 2 < nslots) issue(slot + 2);
    }

    // ---- partial-gate write path (l1a) ----
    const size_t pgbase =
        (((size_t)blockIdx.x * 8 + blockIdx.y) * THREADS + tid) * 16;
    if (P.pgOut != nullptr) {
#pragma unroll
        for (int nt = 0; nt < 4; ++nt)
            *(float4*)(P.pgOut + pgbase + nt * 4) =
                make_float4(acc[nt][0], acc[nt][1], acc[nt][2], acc[nt][3]);
        return;
    }

    // ---- epilogue ----
    const bool doY = (P.ypOut != nullptr);
    float* hsm = (float*)smem_raw;              // 64x32 fp32 staging (slot0 region)
    if (doY) __syncthreads();                   // all warps done reading slots

    const bool odd = (l & 1) != 0;
#pragma unroll
    for (int nt = 0; nt < 4; ++nt) {
        float* cc = acc[nt];
        if (P.pgIn != nullptr) {
            float4 pg = *(const float4*)(P.pgIn + pgbase + nt * 4);
            cc[0] += pg.x; cc[1] += pg.y; cc[2] += pg.z; cc[3] += pg.w;
        }
        float send1 = odd ? cc[0] : cc[2];
        float send2 = odd ? cc[1] : cc[3];
        float r1 = __shfl_xor_sync(0xffffffffu, send1, 1);
        float r2 = __shfl_xor_sync(0xffffffffu, send2, 1);
        float gi, gf, gg, go;
        if (!odd) { gi = cc[0]; gf = cc[1]; gg = r1; go = r2; }
        else      { gi = r1;    gf = r2;    gg = cc[2]; go = cc[3]; }

        const int j = ((n0 + wn * 32 + nt * 8) >> 2) + ((l & 3) >> 1);
        const float4 b4 = *(const float4*)(P.bias + 4 * j);
        gi += b4.x; gf += b4.y; gg += b4.z; go += b4.w;

        const int row = wm * 16 + (l >> 2) + (odd ? 8 : 0);
        const int bglob = m0 + row;
        const int ix = bglob * HID + j;
        float cp = P.cbuf[ix];
        float cn = sigf(gf) * cp + sigf(gi) * tanhf(gg);
        float hn = sigf(go) * tanhf(cn);
        P.cbuf[ix] = cn;
        P.hOut[((size_t)(j >> 6) * BATCH + bglob) * 64 + swz(j & 63, bglob)] =
            __float2half(hn);
        if (P.hOutF != nullptr) P.hOutF[ix] = hn;
        if (doY) {
            const int jj = wn * 8 + nt * 2 + ((l & 3) >> 1);
            hsm[row * 32 + jj] = hn;
        }
    }

    // ---- partial fc: y_part(b,o) over this CTA's 32 hidden units ----
    if (doY) {
        __syncthreads();
        const int row2 = tid >> 3, o = tid & 7;
        const float* wrow = P.fcw + (size_t)o * HID + (n0 >> 2);
        float y = 0.0f;
#pragma unroll
        for (int jj = 0; jj < 32; ++jj)
            y += __ldg(wrow + jj) * hsm[row2 * 32 + jj];
        P.ypOut[((size_t)blockIdx.x * BATCH + (m0 + row2)) * OUT_DIM + o] = y;
    }
}

// ---------------- final output row (gathers h1f) ----------------
__global__ void fc_out(const float* __restrict__ h1f,
                       const float* __restrict__ fcw, const float* __restrict__ fcb,
                       float* __restrict__ outp) {
    int idx = blockIdx.x * blockDim.x + threadIdx.x;   // 4096
    int b = idx >> 3, o = idx & 7;
    const float4* h4 = (const float4*)(h1f + (size_t)b * HID);
    const float4* w4 = (const float4*)(fcw + (size_t)o * HID);
    float s = fcb[o];
#pragma unroll 4
    for (int j = 0; j < HID / 4; ++j) {
        float4 a = h4[j], wv = w4[j];
        s += a.x * wv.x + a.y * wv.y + a.z * wv.z + a.w * wv.w;
    }
    outp[b * OUT_DIM + o] = s;
}

// ---------------- host orchestration ----------------
extern "C" void kernel_launch(void* const* d_in, const int* in_sizes, int n_in,
                              void* d_out, int out_size) {
    const float* x     = (const float*)d_in[0];
    const float* ft    = (const float*)d_in[1];
    const float* h0in  = (const float*)d_in[2];
    const float* c0in  = (const float*)d_in[3];
    const float* w_ih0 = (const float*)d_in[4];
    const float* w_hh0 = (const float*)d_in[5];
    const float* b_ih0 = (const float*)d_in[6];
    const float* b_hh0 = (const float*)d_in[7];
    const float* w_ih1 = (const float*)d_in[8];
    const float* w_hh1 = (const float*)d_in[9];
    const float* b_ih1 = (const float*)d_in[10];
    const float* b_hh1 = (const float*)d_in[11];
    const float* fcw   = (const float*)d_in[12];
    const float* fcb   = (const float*)d_in[13];
    float* out = (float*)d_out;

    cudaFuncSetAttribute(lstm_cell, cudaFuncAttributeMaxDynamicSharedMemorySize, SMEM_B);

    __half *w0p, *w1p, *xp, *h0p, *h1p;
    float *h1fp, *pgp, *ypp, *c0p, *c1p, *b0p, *b1p;
    cudaGetSymbolAddress((void**)&w0p, g_w0);
    cudaGetSymbolAddress((void**)&w1p, g_w1);
    cudaGetSymbolAddress((void**)&xp, g_xp);
    cudaGetSymbolAddress((void**)&h0p, g_h0);
    cudaGetSymbolAddress((void**)&h1p, g_h1);
    cudaGetSymbolAddress((void**)&h1fp, g_h1f);
    cudaGetSymbolAddress((void**)&pgp, g_pg);
    cudaGetSymbolAddress((void**)&ypp, g_yp);
    cudaGetSymbolAddress((void**)&c0p, g_c0);
    cudaGetSymbolAddress((void**)&c1p, g_c1);
    cudaGetSymbolAddress((void**)&b0p, g_b0);
    cudaGetSymbolAddress((void**)&b1p, g_b1);

    prep_w0<<<(G4 * (64 + HID) + 255) / 256, 256>>>(w_ih0, w_hh0);
    prep_w1<<<(G4 * 1024 + 255) / 256, 256>>>(w_ih1, w_hh1);
    prep_misc<<<(SEQ * BATCH * 64 + 255) / 256, 256>>>(x, h0in, c0in,
                                                       b_ih0, b_hh0, b_ih1, b_hh1);

    const int SN = BATCH * HID;
    CellP Z = {};

    auto mk_l0enc = [&](int s) {
        CellP a = {};
        a.slab0 = xp + (size_t)s * BATCH * 64;
        a.a1 = h0p + (size_t)(s & 1) * SN;
        a.wt = w0p; a.nch = NCH0; a.woff = 0; a.wstride = NCH0;
        a.bias = b0p; a.cbuf = c0p;
        a.hOut = h0p + (size_t)((s + 1) & 1) * SN;
        return a;
    };
    auto mk_l1full = [&](int s, bool yfc) {
        CellP a = {};
        a.a1 = h0p + (size_t)((s + 1) & 1) * SN;
        a.a2 = h1p + (size_t)(s & 1) * SN;
        a.wt = w1p; a.nch = NCH1; a.woff = 0; a.wstride = NCH1;
        a.bias = b1p; a.cbuf = c1p;
        a.hOut = h1p + (size_t)((s + 1) & 1) * SN;
        if (yfc) { a.ypOut = ypp; a.fcw = fcw; }
        return a;
    };
    auto mk_l0dec = [&](int s, int d) {   // light gather prologue, writes out[d]
        CellP a = {};
        a.a1 = h0p + (size_t)(s & 1) * SN;
        a.wt = w0p; a.nch = NCH0; a.woff = 0; a.wstride = NCH0;
        a.bias = b0p; a.cbuf = c0p;
        a.hOut = h0p + (size_t)((s + 1) & 1) * SN;
        a.ypIn = ypp; a.fcb = fcb;
        a.tfrow = ft + (size_t)d * BATCH * TF_DIM;
        a.outrow = out + (size_t)d * BATCH * OUT_DIM;
        return a;
    };
    auto mk_l1a = [&](int s) {   // h1_old half -> partial gates
        CellP a = {};
        a.a1 = h1p + (size_t)(s & 1) * SN;
        a.wt = w1p; a.nch = 8; a.woff = 8; a.wstride = NCH1;
        a.pgOut = pgp;
        return a;
    };
    auto mk_l1b = [&](int s, bool lastF) {   // h0_new half + partial add + fc partials
        CellP a = {};
        a.a1 = h0p + (size_t)((s + 1) & 1) * SN;
        a.wt = w1p; a.nch = 8; a.woff = 0; a.wstride = NCH1;
        a.pgIn = pgp;
        a.bias = b1p; a.cbuf = c1p;
        a.hOut = h1p + (size_t)((s + 1) & 1) * SN;
        a.ypOut = ypp; a.fcw = fcw;
        a.hOutF = lastF ? h1fp : nullptr;
        return a;
    };

    const dim3 gridS(16, 8, 1), gridC(16, 8, 2);

    // encoder: pair l1(t) with independent l0(t+1)
    lstm_cell<<<gridS, THREADS, SMEM_B>>>(mk_l0enc(0), Z);
    for (int t = 0; t < SEQ - 1; ++t)
        lstm_cell<<<gridC, THREADS, SMEM_B>>>(mk_l1full(t, false), mk_l0enc(t + 1));
    lstm_cell<<<gridS, THREADS, SMEM_B>>>(mk_l1full(SEQ - 1, true), Z);

    // decode: pairC(l0dec-gather(d), l1a(d)) -> l1b(d, +fc partials); 2 launches/step
    for (int d = 0; d < FUT - 1; ++d) {
        const int s = SEQ + d;
        lstm_cell<<<gridC, THREADS, SMEM_B>>>(mk_l0dec(s, d), mk_l1a(s));
        lstm_cell<<<gridS, THREADS, SMEM_B>>>(mk_l1b(s, d == FUT - 2), Z);
    }
    fc_out<<<16, 256>>>(h1fp, fcw, fcb, out + (size_t)(FUT - 1) * BATCH * OUT_DIM);
}